// round 14
// baseline (speedup 1.0000x reference)
#include <cuda_runtime.h>
#include <cuda_fp16.h>
#include <math.h>
#include <stdint.h>

#define NROWS 8192
#define DIM 512
#define LOGIT_SCALE 2.659f
#define QSCALE 16.0f          // feature pre-scale before e4m3 quantization
#define INV_QS2 (1.0f / (QSCALE * QSCALE))
#define NTILES 2048           // 32 (j) x 64 (i)
#define PGRID 296             // persistent CTAs: 2 per SM x 148

// ---------------- device scratch ----------------
__device__ uint8_t g_A8[NROWS * DIM];   // normalized image features (e4m3, x16)
__device__ uint8_t g_B8[NROWS * DIM];   // normalized text features (e4m3, x16)
__device__ float g_rowZ[NROWS], g_rowS[NROWS], g_colZ[NROWS], g_colS[NROWS];
__device__ int   g_lab[NROWS];
__device__ int   g_hist[1024];          // reset by last k_gemm CTA (replay safe)
__device__ int   g_rc[64];              // per-i-tile-row completion counters
__device__ int   g_cc[32];              // per-j-tile-col completion counters
__device__ int   g_done;                // global CTA completion counter
__device__ float g_loss;                // accumulated total loss

// ---------------- fast exp on the FMA pipe (|x| <= ~3, rel err ~2e-6) ----------------
__device__ __forceinline__ float fexp(float s) {
    float t = s * 1.4426950408889634f;
    float z = t + 12582912.0f;
    int   n = __float_as_int(z) - 0x4B400000;
    float nf = z - 12582912.0f;
    float f = t - nf;
    float p = 1.3333558146e-3f;
    p = fmaf(p, f, 9.6181291076e-3f);
    p = fmaf(p, f, 5.5504108665e-2f);
    p = fmaf(p, f, 2.4022650696e-1f);
    p = fmaf(p, f, 6.9314718056e-1f);
    p = fmaf(p, f, 1.0f);
    return __int_as_float(__float_as_int(p) + (n << 23));
}

// ---------------- async copy helpers ----------------
#define CP_ASYNC16(dst, src) \
    asm volatile("cp.async.cg.shared.global [%0], [%1], 16;" :: "r"(dst), "l"(src))
#define CP_COMMIT() asm volatile("cp.async.commit_group;" ::: "memory")
#define CP_WAIT(n)  asm volatile("cp.async.wait_group %0;" :: "n"(n) : "memory")

__device__ __forceinline__ uint32_t smem_u32(const void* p) {
    uint32_t a;
    asm("{ .reg .u64 t; cvta.to.shared.u64 t, %1; cvt.u32.u64 %0, t; }" : "=r"(a) : "l"(p));
    return a;
}

__device__ __forceinline__ void ldmatrix_x4(uint32_t& r0, uint32_t& r1, uint32_t& r2,
                                            uint32_t& r3, uint32_t addr) {
    asm volatile("ldmatrix.sync.aligned.m8n8.x4.shared.b16 {%0,%1,%2,%3}, [%4];"
                 : "=r"(r0), "=r"(r1), "=r"(r2), "=r"(r3) : "r"(addr));
}

// e4m3 x e4m3 -> f16 accumulate, m16n8k32 (acc: 2 regs of half2)
__device__ __forceinline__ void mma_fp8_f16(uint32_t* d, const uint32_t* a,
                                            uint32_t b0, uint32_t b1) {
    asm volatile(
        "mma.sync.aligned.m16n8k32.row.col.f16.e4m3.e4m3.f16 "
        "{%0,%1}, {%2,%3,%4,%5}, {%6,%7}, {%0,%1};"
        : "+r"(d[0]), "+r"(d[1])
        : "r"(a[0]), "r"(a[1]), "r"(a[2]), "r"(a[3]), "r"(b0), "r"(b1));
}

// pack two floats into two e4m3 bytes (hi, lo)
__device__ __forceinline__ uint16_t pack_e4m3x2(float hi, float lo) {
    uint16_t r;
    asm("cvt.rn.satfinite.e4m3x2.f32 %0, %1, %2;" : "=h"(r) : "f"(hi), "f"(lo));
    return r;
}

// ---------------- launch 0: normalize/cast + (blocks 0..31) label init ----------------
__global__ void k_norm(const float* __restrict__ img, const float* __restrict__ txt,
                       const int* __restrict__ w) {
    if (blockIdx.x < 32) {
        __shared__ int s_is64;
        int ok = 1;
        for (int p = threadIdx.x; p < 4096; p += 256) {
            int lo = w[2 * p], hi = w[2 * p + 1];
            if (hi != (lo >> 31)) ok = 0;
        }
        ok = __syncthreads_and(ok);
        if (threadIdx.x == 0) s_is64 = ok;
        __syncthreads();
        int i = blockIdx.x * 256 + threadIdx.x;
        int lab = s_is64 ? (int)((const long long*)w)[i] : w[i];
        g_lab[i] = lab;
        if (lab >= 0) atomicAdd(&g_hist[lab & 1023], 1);
        g_rowZ[i] = 0.f; g_rowS[i] = 0.f;
        g_colZ[i] = 0.f; g_colS[i] = 0.f;
    }

    int wgl = blockIdx.x * 8 + (threadIdx.x >> 5);   // global warp id: 0..16383
    int lane = threadIdx.x & 31;
    const float* src; uint8_t* dst; int row;
    if (wgl < NROWS) { src = img; dst = g_A8; row = wgl; }
    else             { src = txt; dst = g_B8; row = wgl - NROWS; }
    const float4* p = (const float4*)(src + (size_t)row * DIM) + lane * 4;
    float4 v0 = p[0], v1 = p[1], v2 = p[2], v3 = p[3];
    float ss = v0.x * v0.x + v0.y * v0.y + v0.z * v0.z + v0.w * v0.w
             + v1.x * v1.x + v1.y * v1.y + v1.z * v1.z + v1.w * v1.w
             + v2.x * v2.x + v2.y * v2.y + v2.z * v2.z + v2.w * v2.w
             + v3.x * v3.x + v3.y * v3.y + v3.z * v3.z + v3.w * v3.w;
#pragma unroll
    for (int m = 16; m; m >>= 1) ss += __shfl_xor_sync(0xffffffffu, ss, m);
    float inv = QSCALE * rsqrtf(fmaxf(ss, 1e-24f));
    uint4 o;
    o.x = (uint32_t)pack_e4m3x2(v0.y * inv, v0.x * inv)
        | ((uint32_t)pack_e4m3x2(v0.w * inv, v0.z * inv) << 16);
    o.y = (uint32_t)pack_e4m3x2(v1.y * inv, v1.x * inv)
        | ((uint32_t)pack_e4m3x2(v1.w * inv, v1.z * inv) << 16);
    o.z = (uint32_t)pack_e4m3x2(v2.y * inv, v2.x * inv)
        | ((uint32_t)pack_e4m3x2(v2.w * inv, v2.z * inv) << 16);
    o.w = (uint32_t)pack_e4m3x2(v3.y * inv, v3.x * inv)
        | ((uint32_t)pack_e4m3x2(v3.w * inv, v3.z * inv) << 16);
    *(uint4*)(dst + (size_t)row * DIM + lane * 16) = o;
}

// ---------------- launch 1: persistent fused fp8 GEMM + stats + reduce + output ----------------
// 296 persistent CTAs (2/SM); each loops over tiles bid, bid+296, ... of the
// 32x64 tile grid. The cp.async stage stream is continuous ACROSS tiles: the
// last k-chunk of tile t issues tile t+296's chunk 0, so each tile's epilogue
// overlaps the next tile's loads and wave transitions vanish.
// CTA tile 128(m) x 256(n), BK=128B, 2 slots, 8 warps (2m x 4n), f16 acc.
#define STAGE_BYTES 49152

__global__ __launch_bounds__(256, 2) void k_gemm(float* __restrict__ out) {
    extern __shared__ char smem[];
    const uint32_t sbase = smem_u32(smem);
    const int tid = threadIdx.x;
    const int lane = tid & 31, wid = tid >> 5;
    const int wm = wid & 1, wn = wid >> 1;            // 2 x 4 warp grid

    const int g = lane >> 3;         // lane group 0..3
    const int lr = lane & 7;
    const uint32_t aBase = (uint32_t)(wm * 8192 + (g & 1) * 1024 + (g >> 1) * 128 + lr * 16);
    const uint32_t bBase = (uint32_t)(16384 + wn * 8192 + (g >> 1) * 1024 + (g & 1) * 128 + lr * 16);

    // loader geometry: 256 threads; A 1024 vec16 (4/thread), B 2048 vec16 (8/thread)
    const int r0  = tid >> 3;        // 0..31
    const int seg = tid & 7;         // 16B chunk within the 128B stage row
    const uint32_t dBase = (uint32_t)(((r0 >> 3) * 8 + seg) * 128 + (r0 & 7) * 16);
    const size_t thrOff = (size_t)r0 * DIM + seg * 16;

    // issue one BK=128 chunk of tile t into slot s
    auto load_chunk = [&](int s, int t, int kk) {
        int ti = t >> 5, tj = t & 31;                 // i-tile, j-tile
        const uint8_t* pA = g_A8 + (size_t)(ti * 128) * DIM + thrOff + kk;
        const uint8_t* pB = g_B8 + (size_t)(tj * 256) * DIM + thrOff + kk;
        uint32_t sA = sbase + s * STAGE_BYTES;
        uint32_t sB = sA + 16384;
#pragma unroll
        for (int q = 0; q < 4; q++)
            CP_ASYNC16(sA + dBase + q * 4096, pA + (size_t)(32 * q) * DIM);
#pragma unroll
        for (int q = 0; q < 8; q++)
            CP_ASYNC16(sB + dBase + q * 4096, pB + (size_t)(32 * q) * DIM);
    };

    int slot = 0;
    load_chunk(0, blockIdx.x, 0);
    CP_COMMIT();

    for (int t = blockIdx.x; t < NTILES; t += PGRID) {
        const int i0 = (t >> 5) * 128, j0 = (t & 31) * 256;

        uint32_t acc[4][8][2];   // f16 accumulators (half2 pairs), warp tile 64x64
#pragma unroll
        for (int mt = 0; mt < 4; mt++)
#pragma unroll
            for (int nt = 0; nt < 8; nt++) { acc[mt][nt][0] = 0u; acc[mt][nt][1] = 0u; }

        for (int it = 0; it < 4; it++) {
            CP_WAIT(0);
            __syncthreads();
            if (it < 3)                       load_chunk(slot ^ 1, t, (it + 1) * 128);
            else if (t + PGRID < NTILES)      load_chunk(slot ^ 1, t + PGRID, 0);
            CP_COMMIT();
            uint32_t stg = sbase + slot * STAGE_BYTES;
#pragma unroll
            for (int ks = 0; ks < 4; ks++) {
                uint32_t A[4][4];
#pragma unroll
                for (int mt = 0; mt < 4; mt++)
                    ldmatrix_x4(A[mt][0], A[mt][1], A[mt][2], A[mt][3],
                                stg + aBase + mt * 2048 + ks * 256);
                uint32_t Bc[4], Bn[4];
                ldmatrix_x4(Bc[0], Bc[1], Bc[2], Bc[3], stg + bBase + ks * 256);
#pragma unroll
                for (int np = 0; np < 4; np++) {
                    if (np < 3)
                        ldmatrix_x4(Bn[0], Bn[1], Bn[2], Bn[3],
                                    stg + bBase + (np + 1) * 2048 + ks * 256);
#pragma unroll
                    for (int mt = 0; mt < 4; mt++) {
                        mma_fp8_f16(acc[mt][np * 2],     A[mt], Bc[0], Bc[1]);
                        mma_fp8_f16(acc[mt][np * 2 + 1], A[mt], Bc[2], Bc[3]);
                    }
#pragma unroll
                    for (int q = 0; q < 4; q++) Bc[q] = Bn[q];
                }
            }
            slot ^= 1;
        }

        // ---- epilogue (overlaps the in-flight loads of the next tile) ----
        const int r_base = i0 + wm * 64 + (lane >> 2);
        const int c_base = j0 + wn * 64 + 2 * (lane & 3);
        const float lsc = LOGIT_SCALE * INV_QS2;

        int labR[8];
#pragma unroll
        for (int q = 0; q < 8; q++) labR[q] = g_lab[r_base + (q >> 1) * 16 + (q & 1) * 8];
        int labC[16];
#pragma unroll
        for (int nt = 0; nt < 8; nt++) {
            labC[nt * 2]     = g_lab[c_base + nt * 8];
            labC[nt * 2 + 1] = g_lab[c_base + nt * 8 + 1];
        }

        float rZ[8], rS[8], cZ[16], cS[16];
#pragma unroll
        for (int q = 0; q < 8; q++) { rZ[q] = 0.f; rS[q] = 0.f; }
#pragma unroll
        for (int q = 0; q < 16; q++) { cZ[q] = 0.f; cS[q] = 0.f; }

#pragma unroll
        for (int mt = 0; mt < 4; mt++)
#pragma unroll
            for (int nt = 0; nt < 8; nt++)
#pragma unroll
                for (int hb = 0; hb < 2; hb++) {
                    float2 pv = __half22float2(*(__half2*)&acc[mt][nt][hb]);
                    int gi = r_base + mt * 16 + hb * 8;
                    int li = labR[mt * 2 + hb];
#pragma unroll
                    for (int d = 0; d < 2; d++) {
                        float sv = lsc * (d ? pv.y : pv.x);
                        float ex = fexp(sv);
                        int gj = c_base + nt * 8 + d;
                        bool tg = (gi == gj) || (li >= 0 && li == labC[nt * 2 + d]);
                        float ms = tg ? sv : 0.f;
                        rZ[mt * 2 + hb] += ex; rS[mt * 2 + hb] += ms;
                        cZ[nt * 2 + d] += ex;  cS[nt * 2 + d] += ms;
                    }
                }

#pragma unroll
        for (int m = 1; m <= 2; m <<= 1)
#pragma unroll
            for (int q = 0; q < 8; q++) {
                rZ[q] += __shfl_xor_sync(0xffffffffu, rZ[q], m);
                rS[q] += __shfl_xor_sync(0xffffffffu, rS[q], m);
            }
        if ((lane & 3) == 0) {
#pragma unroll
            for (int q = 0; q < 8; q++) {
                int gi = r_base + (q >> 1) * 16 + (q & 1) * 8;
                atomicAdd(&g_rowZ[gi], rZ[q]);
                atomicAdd(&g_rowS[gi], rS[q]);
            }
        }

#pragma unroll
        for (int m = 4; m <= 16; m <<= 1)
#pragma unroll
            for (int q = 0; q < 16; q++) {
                cZ[q] += __shfl_xor_sync(0xffffffffu, cZ[q], m);
                cS[q] += __shfl_xor_sync(0xffffffffu, cS[q], m);
            }
        if (lane < 4) {
#pragma unroll
            for (int q = 0; q < 16; q++) {
                int gj = j0 + wn * 64 + (q >> 1) * 8 + 2 * lane + (q & 1);
                atomicAdd(&g_colZ[gj], cZ[q]);
                atomicAdd(&g_colS[gj], cS[q]);
            }
        }

        // ---- per-tile distributed reduction ----
        __threadfence();
        __syncthreads();
        __shared__ int fR, fC;
        if (tid == 0) {
            fR = (atomicAdd(&g_rc[t >> 5], 1) == 31);   // last of 32 j-tiles
            fC = (atomicAdd(&g_cc[t & 31], 1) == 63);   // last of 64 i-tiles
        }
        __syncthreads();

        if (fR) {
            __threadfence();
            float part = 0.f;
            if (tid < 128) {
                int i = i0 + tid;
                int l = g_lab[i];
                float inv = (l < 0) ? 1.f : 1.f / (float)g_hist[l & 1023];
                part = logf(__ldcg(&g_rowZ[i])) - __ldcg(&g_rowS[i]) * inv;
            }
#pragma unroll
            for (int m = 16; m; m >>= 1) part += __shfl_xor_sync(0xffffffffu, part, m);
            if (lane == 0 && wid < 4) atomicAdd(&g_loss, part);
        }
        if (fC) {
            __threadfence();
            int j = j0 + tid;
            int l = g_lab[j];
            float inv = (l < 0) ? 1.f : 1.f / (float)g_hist[l & 1023];
            float part = logf(__ldcg(&g_colZ[j])) - __ldcg(&g_colS[j]) * inv;
#pragma unroll
            for (int m = 16; m; m >>= 1) part += __shfl_xor_sync(0xffffffffu, part, m);
            if (lane == 0) atomicAdd(&g_loss, part);
        }
        __syncthreads();   // fR/fC smem reuse safety for next tile
    }

    // ---- global completion: last CTA emits the result + resets replay state ----
    __threadfence();
    __syncthreads();
    __shared__ int fLast;
    if (tid == 0) fLast = (atomicAdd(&g_done, 1) == PGRID - 1);
    __syncthreads();
    if (fLast) {
        __threadfence();
        if (tid == 0) {
            out[0] = __ldcg(&g_loss) / (2.0f * NROWS);
            g_loss = 0.f;
            g_done = 0;
        }
        if (tid < 64) g_rc[tid] = 0;
        if (tid < 32) g_cc[tid] = 0;
        for (int i = tid; i < 1024; i += 256) g_hist[i] = 0;
    }
}

// ---------------- launch ----------------
extern "C" void kernel_launch(void* const* d_in, const int* in_sizes, int n_in,
                              void* d_out, int out_size) {
    const float* txt = (const float*)d_in[0];
    const float* img = (const float*)d_in[1];
    const int*   lab = (const int*)d_in[2];

    cudaFuncSetAttribute(k_gemm, cudaFuncAttributeMaxDynamicSharedMemorySize,
                         2 * STAGE_BYTES);

    k_norm<<<2048, 256>>>(img, txt, lab);                    // launch 0 (norm + init)
    k_gemm<<<PGRID, 256, 2 * STAGE_BYTES>>>((float*)d_out);  // launch 1 (persistent)
}

// round 15
// speedup vs baseline: 1.1202x; 1.1202x over previous
#include <cuda_runtime.h>
#include <cuda_fp16.h>
#include <math.h>
#include <stdint.h>

#define NROWS 8192
#define DIM 512
#define LOGIT_SCALE 2.659f
#define QSCALE 16.0f          // feature pre-scale before e4m3 quantization
#define INV_QS2 (1.0f / (QSCALE * QSCALE))

// ---------------- device scratch ----------------
__device__ uint8_t g_A8[NROWS * DIM];   // normalized image features (e4m3, x16)
__device__ uint8_t g_B8[NROWS * DIM];   // normalized text features (e4m3, x16)
__device__ float g_rowZ[NROWS], g_rowS[NROWS], g_colZ[NROWS], g_colS[NROWS];
__device__ int   g_lab[NROWS];
__device__ int   g_hist[1024];          // reset by last k_gemm CTA (replay safe)
__device__ int   g_rc[64];              // per-i-tile-row completion counters
__device__ int   g_cc[32];              // per-j-tile-col completion counters
__device__ int   g_done;                // global completion counter
__device__ float g_loss;                // accumulated total loss

// ---------------- fast exp on the FMA pipe (|x| <= ~3, rel err ~2e-6) ----------------
__device__ __forceinline__ float fexp(float s) {
    float t = s * 1.4426950408889634f;
    float z = t + 12582912.0f;
    int   n = __float_as_int(z) - 0x4B400000;
    float nf = z - 12582912.0f;
    float f = t - nf;
    float p = 1.3333558146e-3f;
    p = fmaf(p, f, 9.6181291076e-3f);
    p = fmaf(p, f, 5.5504108665e-2f);
    p = fmaf(p, f, 2.4022650696e-1f);
    p = fmaf(p, f, 6.9314718056e-1f);
    p = fmaf(p, f, 1.0f);
    return __int_as_float(__float_as_int(p) + (n << 23));
}

// ---------------- async copy helpers ----------------
#define CP_ASYNC16(dst, src) \
    asm volatile("cp.async.cg.shared.global [%0], [%1], 16;" :: "r"(dst), "l"(src))
#define CP_COMMIT() asm volatile("cp.async.commit_group;" ::: "memory")
#define CP_WAIT(n)  asm volatile("cp.async.wait_group %0;" :: "n"(n) : "memory")

__device__ __forceinline__ uint32_t smem_u32(const void* p) {
    uint32_t a;
    asm("{ .reg .u64 t; cvta.to.shared.u64 t, %1; cvt.u32.u64 %0, t; }" : "=r"(a) : "l"(p));
    return a;
}

__device__ __forceinline__ void ldmatrix_x4(uint32_t& r0, uint32_t& r1, uint32_t& r2,
                                            uint32_t& r3, uint32_t addr) {
    asm volatile("ldmatrix.sync.aligned.m8n8.x4.shared.b16 {%0,%1,%2,%3}, [%4];"
                 : "=r"(r0), "=r"(r1), "=r"(r2), "=r"(r3) : "r"(addr));
}

// e4m3 x e4m3 -> f16 accumulate, m16n8k32 (acc: 2 regs of half2)
__device__ __forceinline__ void mma_fp8_f16(uint32_t* d, const uint32_t* a,
                                            uint32_t b0, uint32_t b1) {
    asm volatile(
        "mma.sync.aligned.m16n8k32.row.col.f16.e4m3.e4m3.f16 "
        "{%0,%1}, {%2,%3,%4,%5}, {%6,%7}, {%0,%1};"
        : "+r"(d[0]), "+r"(d[1])
        : "r"(a[0]), "r"(a[1]), "r"(a[2]), "r"(a[3]), "r"(b0), "r"(b1));
}

// pack two floats into two e4m3 bytes (hi, lo)
__device__ __forceinline__ uint16_t pack_e4m3x2(float hi, float lo) {
    uint16_t r;
    asm("cvt.rn.satfinite.e4m3x2.f32 %0, %1, %2;" : "=h"(r) : "f"(hi), "f"(lo));
    return r;
}

// ---------------- launch 0: normalize/cast + (blocks 0..31) label init ----------------
__global__ void k_norm(const float* __restrict__ img, const float* __restrict__ txt,
                       const int* __restrict__ w) {
    if (blockIdx.x < 32) {
        __shared__ int s_is64;
        int ok = 1;
        for (int p = threadIdx.x; p < 4096; p += 256) {
            int lo = w[2 * p], hi = w[2 * p + 1];
            if (hi != (lo >> 31)) ok = 0;
        }
        ok = __syncthreads_and(ok);
        if (threadIdx.x == 0) s_is64 = ok;
        __syncthreads();
        int i = blockIdx.x * 256 + threadIdx.x;
        int lab = s_is64 ? (int)((const long long*)w)[i] : w[i];
        g_lab[i] = lab;
        if (lab >= 0) atomicAdd(&g_hist[lab & 1023], 1);
        g_rowZ[i] = 0.f; g_rowS[i] = 0.f;
        g_colZ[i] = 0.f; g_colS[i] = 0.f;
    }

    int wgl = blockIdx.x * 8 + (threadIdx.x >> 5);   // global warp id: 0..16383
    int lane = threadIdx.x & 31;
    const float* src; uint8_t* dst; int row;
    if (wgl < NROWS) { src = img; dst = g_A8; row = wgl; }
    else             { src = txt; dst = g_B8; row = wgl - NROWS; }
    const float4* p = (const float4*)(src + (size_t)row * DIM) + lane * 4;
    float4 v0 = p[0], v1 = p[1], v2 = p[2], v3 = p[3];
    float ss = v0.x * v0.x + v0.y * v0.y + v0.z * v0.z + v0.w * v0.w
             + v1.x * v1.x + v1.y * v1.y + v1.z * v1.z + v1.w * v1.w
             + v2.x * v2.x + v2.y * v2.y + v2.z * v2.z + v2.w * v2.w
             + v3.x * v3.x + v3.y * v3.y + v3.z * v3.z + v3.w * v3.w;
#pragma unroll
    for (int m = 16; m; m >>= 1) ss += __shfl_xor_sync(0xffffffffu, ss, m);
    float inv = QSCALE * rsqrtf(fmaxf(ss, 1e-24f));
    uint4 o;
    o.x = (uint32_t)pack_e4m3x2(v0.y * inv, v0.x * inv)
        | ((uint32_t)pack_e4m3x2(v0.w * inv, v0.z * inv) << 16);
    o.y = (uint32_t)pack_e4m3x2(v1.y * inv, v1.x * inv)
        | ((uint32_t)pack_e4m3x2(v1.w * inv, v1.z * inv) << 16);
    o.z = (uint32_t)pack_e4m3x2(v2.y * inv, v2.x * inv)
        | ((uint32_t)pack_e4m3x2(v2.w * inv, v2.z * inv) << 16);
    o.w = (uint32_t)pack_e4m3x2(v3.y * inv, v3.x * inv)
        | ((uint32_t)pack_e4m3x2(v3.w * inv, v3.z * inv) << 16);
    *(uint4*)(dst + (size_t)row * DIM + lane * 16) = o;
}

// ---------------- launch 1: fused fp8 GEMM + stats + distributed reduce + output ----------------
// (R13 configuration — best known.) CTA tile 128(m) x 256(n), BK=128 bytes,
// 2-stage double buffer, 4 iterations, one barrier per iteration.
// 8 warps (2m x 4n), warp tile 64x64, fp16 acc. 2 CTAs/SM (96KB smem).
#define STAGE_BYTES 49152

__global__ __launch_bounds__(256, 2) void k_gemm(float* __restrict__ out) {
    extern __shared__ char smem[];
    const uint32_t sbase = smem_u32(smem);
    const int tid = threadIdx.x;
    const int lane = tid & 31, wid = tid >> 5;
    const int wm = wid & 1, wn = wid >> 1;            // 2 x 4 warp grid
    const int i0 = blockIdx.y * 128, j0 = blockIdx.x * 256;

    const int g = lane >> 3;         // lane group 0..3
    const int lr = lane & 7;
    const uint32_t aBase = (uint32_t)(wm * 8192 + (g & 1) * 1024 + (g >> 1) * 128 + lr * 16);
    const uint32_t bBase = (uint32_t)(16384 + wn * 8192 + (g >> 1) * 1024 + (g & 1) * 128 + lr * 16);

    // loader: 256 threads; A 1024 vec16 (4/thread), B 2048 vec16 (8/thread)
    const int r0  = tid >> 3;        // 0..31
    const int seg = tid & 7;         // 16B chunk within the 128B stage row
    const uint32_t dBase = (uint32_t)(((r0 >> 3) * 8 + seg) * 128 + (r0 & 7) * 16);
    const uint8_t* pA = g_A8 + (size_t)(i0 + r0) * DIM + seg * 16;
    const uint8_t* pB = g_B8 + (size_t)(j0 + r0) * DIM + seg * 16;

    uint32_t acc[4][8][2];   // f16 accumulators (half2 pairs), warp tile 64x64
#pragma unroll
    for (int mt = 0; mt < 4; mt++)
#pragma unroll
        for (int nt = 0; nt < 8; nt++) { acc[mt][nt][0] = 0u; acc[mt][nt][1] = 0u; }

    auto load_stage = [&](int s, int kk) {
        uint32_t sA = sbase + s * STAGE_BYTES;
        uint32_t sB = sA + 16384;
#pragma unroll
        for (int t = 0; t < 4; t++)
            CP_ASYNC16(sA + dBase + t * 4096, pA + (size_t)(32 * t) * DIM + kk);
#pragma unroll
        for (int t = 0; t < 8; t++)
            CP_ASYNC16(sB + dBase + t * 4096, pB + (size_t)(32 * t) * DIM + kk);
    };

    load_stage(0, 0);
    CP_COMMIT();

    for (int it = 0; it < 4; it++) {
        CP_WAIT(0);
        __syncthreads();
        if (it + 1 < 4) {
            load_stage((it + 1) & 1, (it + 1) * 128);
            CP_COMMIT();
        }
        uint32_t stg = sbase + (it & 1) * STAGE_BYTES;
#pragma unroll
        for (int ks = 0; ks < 4; ks++) {
            uint32_t A[4][4];
#pragma unroll
            for (int mt = 0; mt < 4; mt++)
                ldmatrix_x4(A[mt][0], A[mt][1], A[mt][2], A[mt][3],
                            stg + aBase + mt * 2048 + ks * 256);
            uint32_t Bc[4], Bn[4];
            ldmatrix_x4(Bc[0], Bc[1], Bc[2], Bc[3], stg + bBase + ks * 256);
#pragma unroll
            for (int np = 0; np < 4; np++) {
                if (np < 3)
                    ldmatrix_x4(Bn[0], Bn[1], Bn[2], Bn[3],
                                stg + bBase + (np + 1) * 2048 + ks * 256);
#pragma unroll
                for (int mt = 0; mt < 4; mt++) {
                    mma_fp8_f16(acc[mt][np * 2],     A[mt], Bc[0], Bc[1]);
                    mma_fp8_f16(acc[mt][np * 2 + 1], A[mt], Bc[2], Bc[3]);
                }
#pragma unroll
                for (int q = 0; q < 4; q++) Bc[q] = Bn[q];
            }
        }
    }

    // ---- epilogue: logits -> exp + target-weighted stats (registers only) ----
    const int r_base = i0 + wm * 64 + (lane >> 2);
    const int c_base = j0 + wn * 64 + 2 * (lane & 3);
    const float lsc = LOGIT_SCALE * INV_QS2;

    // sentinel row labels: -1 -> INT_MIN, so the per-element check is one compare
    int labR[8];
#pragma unroll
    for (int q = 0; q < 8; q++) {
        int li = g_lab[r_base + (q >> 1) * 16 + (q & 1) * 8];
        labR[q] = (li < 0) ? 0x80000000 : li;
    }
    int labC[16];
#pragma unroll
    for (int nt = 0; nt < 8; nt++) {
        labC[nt * 2]     = g_lab[c_base + nt * 8];
        labC[nt * 2 + 1] = g_lab[c_base + nt * 8 + 1];
    }

    float rZ[8], rS[8], cZ[16], cS[16];
#pragma unroll
    for (int q = 0; q < 8; q++) { rZ[q] = 0.f; rS[q] = 0.f; }
#pragma unroll
    for (int q = 0; q < 16; q++) { cZ[q] = 0.f; cS[q] = 0.f; }

#pragma unroll
    for (int mt = 0; mt < 4; mt++)
#pragma unroll
        for (int nt = 0; nt < 8; nt++)
#pragma unroll
            for (int hb = 0; hb < 2; hb++) {
                float2 pv = __half22float2(*(__half2*)&acc[mt][nt][hb]);
                int gi = r_base + mt * 16 + hb * 8;
                int liX = labR[mt * 2 + hb];
#pragma unroll
                for (int d = 0; d < 2; d++) {
                    float sv = lsc * (d ? pv.y : pv.x);
                    float ex = fexp(sv);
                    int gj = c_base + nt * 8 + d;
                    bool tg = (gi == gj) | (liX == labC[nt * 2 + d]);
                    float ms = tg ? sv : 0.f;
                    rZ[mt * 2 + hb] += ex; rS[mt * 2 + hb] += ms;
                    cZ[nt * 2 + d] += ex;  cS[nt * 2 + d] += ms;
                }
            }

    // rows: reduce across the 4 lanes of each quad
#pragma unroll
    for (int m = 1; m <= 2; m <<= 1)
#pragma unroll
        for (int q = 0; q < 8; q++) {
            rZ[q] += __shfl_xor_sync(0xffffffffu, rZ[q], m);
            rS[q] += __shfl_xor_sync(0xffffffffu, rS[q], m);
        }
    if ((lane & 3) == 0) {
#pragma unroll
        for (int q = 0; q < 8; q++) {
            int gi = r_base + (q >> 1) * 16 + (q & 1) * 8;
            atomicAdd(&g_rowZ[gi], rZ[q]);
            atomicAdd(&g_rowS[gi], rS[q]);
        }
    }

    // cols: reduce across lane>>2
#pragma unroll
    for (int m = 4; m <= 16; m <<= 1)
#pragma unroll
        for (int q = 0; q < 16; q++) {
            cZ[q] += __shfl_xor_sync(0xffffffffu, cZ[q], m);
            cS[q] += __shfl_xor_sync(0xffffffffu, cS[q], m);
        }
    if (lane < 4) {
#pragma unroll
        for (int q = 0; q < 16; q++) {
            int gj = j0 + wn * 64 + (q >> 1) * 8 + 2 * lane + (q & 1);
            atomicAdd(&g_colZ[gj], cZ[q]);
            atomicAdd(&g_colS[gj], cS[q]);
        }
    }

    // ---- distributed final reduction ----
    __threadfence();          // make this CTA's stat atomics visible
    __syncthreads();
    __shared__ int fR, fC, fLast;
    if (tid == 0) {
        fR = (atomicAdd(&g_rc[blockIdx.y], 1) == 31);   // last of 32 j-tiles
        fC = (atomicAdd(&g_cc[blockIdx.x], 1) == 63);   // last of 64 i-tiles
    }
    __syncthreads();

    if (fR) {                 // rows i0..i0+127 complete: reduce row losses
        __threadfence();
        float part = 0.f;
        if (tid < 128) {
            int i = i0 + tid;
            int l = g_lab[i];
            float inv = (l < 0) ? 1.f : 1.f / (float)g_hist[l & 1023];
            part = __logf(__ldcg(&g_rowZ[i])) - __ldcg(&g_rowS[i]) * inv;
        }
#pragma unroll
        for (int m = 16; m; m >>= 1) part += __shfl_xor_sync(0xffffffffu, part, m);
        if (lane == 0 && wid < 4) atomicAdd(&g_loss, part);
    }
    if (fC) {                 // cols j0..j0+255 complete: reduce col losses
        __threadfence();
        int j = j0 + tid;
        int l = g_lab[j];
        float inv = (l < 0) ? 1.f : 1.f / (float)g_hist[l & 1023];
        float part = __logf(__ldcg(&g_colZ[j])) - __ldcg(&g_colS[j]) * inv;
#pragma unroll
        for (int m = 16; m; m >>= 1) part += __shfl_xor_sync(0xffffffffu, part, m);
        if (lane == 0) atomicAdd(&g_loss, part);
    }

    // ---- global completion: last CTA emits the result + resets replay state ----
    __threadfence();          // loss contributions visible before arrival
    __syncthreads();          // all threads of this CTA past their adds
    if (tid == 0) fLast = (atomicAdd(&g_done, 1) == 2047);
    __syncthreads();
    if (fLast) {
        __threadfence();
        if (tid == 0) {
            out[0] = __ldcg(&g_loss) / (2.0f * NROWS);
            g_loss = 0.f;
            g_done = 0;
        }
        if (tid < 64) g_rc[tid] = 0;
        if (tid < 32) g_cc[tid] = 0;
        for (int i = tid; i < 1024; i += 256) g_hist[i] = 0;
    }
}

// ---------------- launch ----------------
extern "C" void kernel_launch(void* const* d_in, const int* in_sizes, int n_in,
                              void* d_out, int out_size) {
    const float* txt = (const float*)d_in[0];
    const float* img = (const float*)d_in[1];
    const int*   lab = (const int*)d_in[2];

    cudaFuncSetAttribute(k_gemm, cudaFuncAttributeMaxDynamicSharedMemorySize,
                         2 * STAGE_BYTES);

    k_norm<<<2048, 256>>>(img, txt, lab);             // launch 0 (norm + init)
    dim3 grid(32, 64);
    k_gemm<<<grid, 256, 2 * STAGE_BYTES>>>((float*)d_out);  // launch 1 (everything else)
}

// round 16
// speedup vs baseline: 1.1229x; 1.0025x over previous
#include <cuda_runtime.h>
#include <cuda_fp16.h>
#include <math.h>
#include <stdint.h>

#define NROWS 8192
#define DIM 512
#define LOGIT_SCALE 2.659f
#define QSCALE 16.0f          // feature pre-scale before e4m3 quantization
#define INV_QS2 (1.0f / (QSCALE * QSCALE))

// ---------------- device scratch ----------------
__device__ uint8_t g_A8[NROWS * DIM];   // normalized image features (e4m3, x16)
__device__ uint8_t g_B8[NROWS * DIM];   // normalized text features (e4m3, x16)
__device__ float g_rowZ[NROWS], g_rowS[NROWS], g_colZ[NROWS], g_colS[NROWS];
__device__ int   g_lab[NROWS];          // VIRTUAL labels: -1 -> 0x80000000|i (unique)
__device__ int   g_hist[1024];          // reset by last k_gemm CTA (replay safe)
__device__ int   g_rc[64];              // per-i-tile-row completion counters
__device__ int   g_cc[32];              // per-j-tile-col completion counters
__device__ int   g_done;                // global completion counter
__device__ float g_loss;                // accumulated total loss

// ---------------- async copy helpers ----------------
#define CP_ASYNC16(dst, src) \
    asm volatile("cp.async.cg.shared.global [%0], [%1], 16;" :: "r"(dst), "l"(src))
#define CP_COMMIT() asm volatile("cp.async.commit_group;" ::: "memory")
#define CP_WAIT(n)  asm volatile("cp.async.wait_group %0;" :: "n"(n) : "memory")

__device__ __forceinline__ uint32_t smem_u32(const void* p) {
    uint32_t a;
    asm("{ .reg .u64 t; cvta.to.shared.u64 t, %1; cvt.u32.u64 %0, t; }" : "=r"(a) : "l"(p));
    return a;
}

__device__ __forceinline__ void ldmatrix_x4(uint32_t& r0, uint32_t& r1, uint32_t& r2,
                                            uint32_t& r3, uint32_t addr) {
    asm volatile("ldmatrix.sync.aligned.m8n8.x4.shared.b16 {%0,%1,%2,%3}, [%4];"
                 : "=r"(r0), "=r"(r1), "=r"(r2), "=r"(r3) : "r"(addr));
}

// e4m3 x e4m3 -> f16 accumulate, m16n8k32 (acc: 2 regs of half2)
__device__ __forceinline__ void mma_fp8_f16(uint32_t* d, const uint32_t* a,
                                            uint32_t b0, uint32_t b1) {
    asm volatile(
        "mma.sync.aligned.m16n8k32.row.col.f16.e4m3.e4m3.f16 "
        "{%0,%1}, {%2,%3,%4,%5}, {%6,%7}, {%0,%1};"
        : "+r"(d[0]), "+r"(d[1])
        : "r"(a[0]), "r"(a[1]), "r"(a[2]), "r"(a[3]), "r"(b0), "r"(b1));
}

// pack two floats into two e4m3 bytes (hi, lo)
__device__ __forceinline__ uint16_t pack_e4m3x2(float hi, float lo) {
    uint16_t r;
    asm("cvt.rn.satfinite.e4m3x2.f32 %0, %1, %2;" : "=h"(r) : "f"(hi), "f"(lo));
    return r;
}

// ---------------- launch 0: normalize/cast + (blocks 0..31) label init ----------------
__global__ void k_norm(const float* __restrict__ img, const float* __restrict__ txt,
                       const int* __restrict__ w) {
    if (blockIdx.x < 32) {
        __shared__ int s_is64;
        int ok = 1;
        for (int p = threadIdx.x; p < 4096; p += 256) {
            int lo = w[2 * p], hi = w[2 * p + 1];
            if (hi != (lo >> 31)) ok = 0;
        }
        ok = __syncthreads_and(ok);
        if (threadIdx.x == 0) s_is64 = ok;
        __syncthreads();
        int i = blockIdx.x * 256 + threadIdx.x;
        int lab = s_is64 ? (int)((const long long*)w)[i] : w[i];
        if (lab >= 0) atomicAdd(&g_hist[lab & 1023], 1);
        // virtual label: unlabeled rows get a unique negative so that
        // T[i][j] == (vlab[i] == vlab[j]) exactly (diagonal included).
        g_lab[i] = (lab < 0) ? (int)(0x80000000u | (unsigned)i) : lab;
        g_rowZ[i] = 0.f; g_rowS[i] = 0.f;
        g_colZ[i] = 0.f; g_colS[i] = 0.f;
    }

    int wgl = blockIdx.x * 8 + (threadIdx.x >> 5);   // global warp id: 0..16383
    int lane = threadIdx.x & 31;
    const float* src; uint8_t* dst; int row;
    if (wgl < NROWS) { src = img; dst = g_A8; row = wgl; }
    else             { src = txt; dst = g_B8; row = wgl - NROWS; }
    const float4* p = (const float4*)(src + (size_t)row * DIM) + lane * 4;
    float4 v0 = p[0], v1 = p[1], v2 = p[2], v3 = p[3];
    float ss = v0.x * v0.x + v0.y * v0.y + v0.z * v0.z + v0.w * v0.w
             + v1.x * v1.x + v1.y * v1.y + v1.z * v1.z + v1.w * v1.w
             + v2.x * v2.x + v2.y * v2.y + v2.z * v2.z + v2.w * v2.w
             + v3.x * v3.x + v3.y * v3.y + v3.z * v3.z + v3.w * v3.w;
#pragma unroll
    for (int m = 16; m; m >>= 1) ss += __shfl_xor_sync(0xffffffffu, ss, m);
    float inv = QSCALE * rsqrtf(fmaxf(ss, 1e-24f));
    uint4 o;
    o.x = (uint32_t)pack_e4m3x2(v0.y * inv, v0.x * inv)
        | ((uint32_t)pack_e4m3x2(v0.w * inv, v0.z * inv) << 16);
    o.y = (uint32_t)pack_e4m3x2(v1.y * inv, v1.x * inv)
        | ((uint32_t)pack_e4m3x2(v1.w * inv, v1.z * inv) << 16);
    o.z = (uint32_t)pack_e4m3x2(v2.y * inv, v2.x * inv)
        | ((uint32_t)pack_e4m3x2(v2.w * inv, v2.z * inv) << 16);
    o.w = (uint32_t)pack_e4m3x2(v3.y * inv, v3.x * inv)
        | ((uint32_t)pack_e4m3x2(v3.w * inv, v3.z * inv) << 16);
    *(uint4*)(dst + (size_t)row * DIM + lane * 16) = o;
}

// ---------------- launch 1: fused fp8 GEMM + stats + distributed reduce + output ----------------
// (R13 mainloop — best known.) CTA tile 128(m) x 256(n), BK=128 bytes,
// 2-stage double buffer, 4 iterations, one barrier per iteration.
// 8 warps (2m x 4n), warp tile 64x64, fp16 acc. 2 CTAs/SM (96KB smem).
// Epilogue: fp16x2 exp (magic-round + deg-4 HFMA2 poly + packed 2^n scale),
// fp32 accumulation, single-compare virtual-label targets.
#define STAGE_BYTES 49152

__global__ __launch_bounds__(256, 2) void k_gemm(float* __restrict__ out) {
    extern __shared__ char smem[];
    const uint32_t sbase = smem_u32(smem);
    const int tid = threadIdx.x;
    const int lane = tid & 31, wid = tid >> 5;
    const int wm = wid & 1, wn = wid >> 1;            // 2 x 4 warp grid
    const int i0 = blockIdx.y * 128, j0 = blockIdx.x * 256;

    const int g = lane >> 3;         // lane group 0..3
    const int lr = lane & 7;
    const uint32_t aBase = (uint32_t)(wm * 8192 + (g & 1) * 1024 + (g >> 1) * 128 + lr * 16);
    const uint32_t bBase = (uint32_t)(16384 + wn * 8192 + (g >> 1) * 1024 + (g & 1) * 128 + lr * 16);

    // loader: 256 threads; A 1024 vec16 (4/thread), B 2048 vec16 (8/thread)
    const int r0  = tid >> 3;        // 0..31
    const int seg = tid & 7;         // 16B chunk within the 128B stage row
    const uint32_t dBase = (uint32_t)(((r0 >> 3) * 8 + seg) * 128 + (r0 & 7) * 16);
    const uint8_t* pA = g_A8 + (size_t)(i0 + r0) * DIM + seg * 16;
    const uint8_t* pB = g_B8 + (size_t)(j0 + r0) * DIM + seg * 16;

    uint32_t acc[4][8][2];   // f16 accumulators (half2 pairs), warp tile 64x64
#pragma unroll
    for (int mt = 0; mt < 4; mt++)
#pragma unroll
        for (int nt = 0; nt < 8; nt++) { acc[mt][nt][0] = 0u; acc[mt][nt][1] = 0u; }

    auto load_stage = [&](int s, int kk) {
        uint32_t sA = sbase + s * STAGE_BYTES;
        uint32_t sB = sA + 16384;
#pragma unroll
        for (int t = 0; t < 4; t++)
            CP_ASYNC16(sA + dBase + t * 4096, pA + (size_t)(32 * t) * DIM + kk);
#pragma unroll
        for (int t = 0; t < 8; t++)
            CP_ASYNC16(sB + dBase + t * 4096, pB + (size_t)(32 * t) * DIM + kk);
    };

    load_stage(0, 0);
    CP_COMMIT();

    for (int it = 0; it < 4; it++) {
        CP_WAIT(0);
        __syncthreads();
        if (it + 1 < 4) {
            load_stage((it + 1) & 1, (it + 1) * 128);
            CP_COMMIT();
        }
        uint32_t stg = sbase + (it & 1) * STAGE_BYTES;
#pragma unroll
        for (int ks = 0; ks < 4; ks++) {
            uint32_t A[4][4];
#pragma unroll
            for (int mt = 0; mt < 4; mt++)
                ldmatrix_x4(A[mt][0], A[mt][1], A[mt][2], A[mt][3],
                            stg + aBase + mt * 2048 + ks * 256);
            uint32_t Bc[4], Bn[4];
            ldmatrix_x4(Bc[0], Bc[1], Bc[2], Bc[3], stg + bBase + ks * 256);
#pragma unroll
            for (int np = 0; np < 4; np++) {
                if (np < 3)
                    ldmatrix_x4(Bn[0], Bn[1], Bn[2], Bn[3],
                                stg + bBase + (np + 1) * 2048 + ks * 256);
#pragma unroll
                for (int mt = 0; mt < 4; mt++) {
                    mma_fp8_f16(acc[mt][np * 2],     A[mt], Bc[0], Bc[1]);
                    mma_fp8_f16(acc[mt][np * 2 + 1], A[mt], Bc[2], Bc[3]);
                }
#pragma unroll
                for (int q = 0; q < 4; q++) Bc[q] = Bn[q];
            }
        }
    }

    // ---- epilogue: fp16x2 exp + virtual-label targets, fp32 accumulation ----
    // acc value = s * QSCALE^2. t = s*log2e = acc * (lsc*log2e). |t| <= ~3.9.
    const int r_base = i0 + wm * 64 + (lane >> 2);
    const int c_base = j0 + wn * 64 + 2 * (lane & 3);

    const __half2 cT    = __float2half2_rn(LOGIT_SCALE * INV_QS2 * 1.4426950408889634f);
    const __half2 cLn2  = __float2half2_rn(0.6931471805599453f);
    const __half2 magic = __float2half2_rn(1536.0f);
    const __half2 k4 = __float2half2_rn(9.6181291076e-3f);
    const __half2 k3 = __float2half2_rn(5.5504108665e-2f);
    const __half2 k2 = __float2half2_rn(2.4022650696e-1f);
    const __half2 k1 = __float2half2_rn(6.9314718056e-1f);
    const __half2 one2 = __float2half2_rn(1.0f);

    int labR[8];
#pragma unroll
    for (int q = 0; q < 8; q++) labR[q] = g_lab[r_base + (q >> 1) * 16 + (q & 1) * 8];
    int labC[16];
#pragma unroll
    for (int nt = 0; nt < 8; nt++) {
        labC[nt * 2]     = g_lab[c_base + nt * 8];
        labC[nt * 2 + 1] = g_lab[c_base + nt * 8 + 1];
    }

    float rZ[8], rS[8], cZ[16], cS[16];
#pragma unroll
    for (int q = 0; q < 8; q++) { rZ[q] = 0.f; rS[q] = 0.f; }
#pragma unroll
    for (int q = 0; q < 16; q++) { cZ[q] = 0.f; cS[q] = 0.f; }

#pragma unroll
    for (int mt = 0; mt < 4; mt++)
#pragma unroll
        for (int nt = 0; nt < 8; nt++)
#pragma unroll
            for (int hb = 0; hb < 2; hb++) {
                __half2 a2 = *(__half2*)&acc[mt][nt][hb];
                __half2 t2 = __hmul2(a2, cT);            // s*log2e, 2-wide
                __half2 z2 = __hadd2(t2, magic);         // round to int (fp16 magic)
                __half2 nf2 = __hsub2(z2, magic);        // n as fp16
                __half2 f2 = __hsub2(t2, nf2);           // frac in [-0.5,0.5]
                __half2 p2 = __hfma2(k4, f2, k3);
                p2 = __hfma2(p2, f2, k2);
                p2 = __hfma2(p2, f2, k1);
                p2 = __hfma2(p2, f2, one2);              // 2^f
                uint32_t zb = *(uint32_t*)&z2;
                // lanes of zb = 0x6600+n, n in [-4,4]; build fp16 2^n per lane:
                // ((8+n)<<10) + (7<<10) = (15+n)<<10  (no cross-lane carries)
                uint32_t sc = ((zb - 0x65F865F8u) << 10) + 0x1C001C00u;
                __half2 e2 = __hmul2(p2, *(__half2*)&sc);    // exp(s)
                float2 ef = __half22float2(e2);
                __half2 s2 = __hmul2(t2, cLn2);              // s (for target sums)
                float2 sf = __half22float2(s2);

                int li = labR[mt * 2 + hb];
                rZ[mt * 2 + hb] += ef.x + ef.y;
                cZ[nt * 2]     += ef.x;
                cZ[nt * 2 + 1] += ef.y;
                if (li == labC[nt * 2])     { rS[mt * 2 + hb] += sf.x; cS[nt * 2]     += sf.x; }
                if (li == labC[nt * 2 + 1]) { rS[mt * 2 + hb] += sf.y; cS[nt * 2 + 1] += sf.y; }
            }

    // rows: reduce across the 4 lanes of each quad
#pragma unroll
    for (int m = 1; m <= 2; m <<= 1)
#pragma unroll
        for (int q = 0; q < 8; q++) {
            rZ[q] += __shfl_xor_sync(0xffffffffu, rZ[q], m);
            rS[q] += __shfl_xor_sync(0xffffffffu, rS[q], m);
        }
    if ((lane & 3) == 0) {
#pragma unroll
        for (int q = 0; q < 8; q++) {
            int gi = r_base + (q >> 1) * 16 + (q & 1) * 8;
            atomicAdd(&g_rowZ[gi], rZ[q]);
            atomicAdd(&g_rowS[gi], rS[q]);
        }
    }

    // cols: reduce across lane>>2
#pragma unroll
    for (int m = 4; m <= 16; m <<= 1)
#pragma unroll
        for (int q = 0; q < 16; q++) {
            cZ[q] += __shfl_xor_sync(0xffffffffu, cZ[q], m);
            cS[q] += __shfl_xor_sync(0xffffffffu, cS[q], m);
        }
    if (lane < 4) {
#pragma unroll
        for (int q = 0; q < 16; q++) {
            int gj = j0 + wn * 64 + (q >> 1) * 8 + 2 * lane + (q & 1);
            atomicAdd(&g_colZ[gj], cZ[q]);
            atomicAdd(&g_colS[gj], cS[q]);
        }
    }

    // ---- distributed final reduction ----
    __threadfence();
    __syncthreads();
    __shared__ int fR, fC, fLast;
    if (tid == 0) {
        fR = (atomicAdd(&g_rc[blockIdx.y], 1) == 31);   // last of 32 j-tiles
        fC = (atomicAdd(&g_cc[blockIdx.x], 1) == 63);   // last of 64 i-tiles
    }
    __syncthreads();

    if (fR) {
        __threadfence();
        float part = 0.f;
        if (tid < 128) {
            int i = i0 + tid;
            int l = g_lab[i];
            float inv = (l < 0) ? 1.f : 1.f / (float)g_hist[l & 1023];
            part = __logf(__ldcg(&g_rowZ[i])) - __ldcg(&g_rowS[i]) * inv;
        }
#pragma unroll
        for (int m = 16; m; m >>= 1) part += __shfl_xor_sync(0xffffffffu, part, m);
        if (lane == 0 && wid < 4) atomicAdd(&g_loss, part);
    }
    if (fC) {
        __threadfence();
        int j = j0 + tid;
        int l = g_lab[j];
        float inv = (l < 0) ? 1.f : 1.f / (float)g_hist[l & 1023];
        float part = __logf(__ldcg(&g_colZ[j])) - __ldcg(&g_colS[j]) * inv;
#pragma unroll
        for (int m = 16; m; m >>= 1) part += __shfl_xor_sync(0xffffffffu, part, m);
        if (lane == 0) atomicAdd(&g_loss, part);
    }

    // ---- global completion: last CTA emits the result + resets replay state ----
    __threadfence();
    __syncthreads();
    if (tid == 0) fLast = (atomicAdd(&g_done, 1) == 2047);
    __syncthreads();
    if (fLast) {
        __threadfence();
        if (tid == 0) {
            out[0] = __ldcg(&g_loss) / (2.0f * NROWS);
            g_loss = 0.f;
            g_done = 0;
        }
        if (tid < 64) g_rc[tid] = 0;
        if (tid < 32) g_cc[tid] = 0;
        for (int i = tid; i < 1024; i += 256) g_hist[i] = 0;
    }
}

// ---------------- launch ----------------
extern "C" void kernel_launch(void* const* d_in, const int* in_sizes, int n_in,
                              void* d_out, int out_size) {
    const float* txt = (const float*)d_in[0];
    const float* img = (const float*)d_in[1];
    const int*   lab = (const int*)d_in[2];

    cudaFuncSetAttribute(k_gemm, cudaFuncAttributeMaxDynamicSharedMemorySize,
                         2 * STAGE_BYTES);

    k_norm<<<2048, 256>>>(img, txt, lab);             // launch 0 (norm + init)
    dim3 grid(32, 64);
    k_gemm<<<grid, 256, 2 * STAGE_BYTES>>>((float*)d_out);  // launch 1 (everything else)
}